// round 9
// baseline (speedup 1.0000x reference)
#include <cuda_runtime.h>
#include <cuda_fp16.h>
#include <cstdint>

// Problem constants (shapes fixed by the dataset)
#define MAX_NODES 50000
#define F_IN   32
#define F_OUT  32
#define NB     4
#define K16    (NB * NB)
// Cell-paired Y layout: [n][kx(4)][cell(3)][ky in {cell,cell+1}][ch(32)] fp16.
// Every (kx, cell) chunk is 128 B and 128 B-aligned -> one line per edge read.
#define YPROW  (4 * 3 * 2 * F_OUT)    // 768 halves = 1536 B per node

__device__ __half g_Yp[(size_t)MAX_NODES * YPROW];   // 76.8 MB

struct alignas(16) Half8 { __half2 h[4]; };

// ---------------------------------------------------------------------------
// Kernel 1: zero out, then Y = X @ Wbig via HMMA m16n8k16 (fp16 in, fp32 acc),
// flushed into the cell-paired layout. 256 threads = 8 warps; the block stages
// a 128-node X tile in smem (coalesced), each warp owns one 16-node m-tile.
// D fragments staged per-warp in smem, flushed as 128 B-aligned segments.
// X staging region is UNIONED with the D staging region (X is consumed into
// A-fragments registers before D staging begins).
// ---------------------------------------------------------------------------
#define WPAD  40    // halves per Ws row (80 B stride: ldmatrix conflict-free)
#define DCOLS 264   // 256 data halves + 8 pad (row stride 528 B, conflict-free)
#define XPAD  34    // floats per Xs row

__global__ __launch_bounds__(256, 2) void build_Y_mma(
    const float* __restrict__ x,     // [N, 32] fp32
    const float* __restrict__ w,     // [16, 32, 32] fp32
    float4*      __restrict__ out4,  // [N*32/4] -- zeroed here
    int n_nodes, int ngroups)
{
    extern __shared__ __half smem[];
    __half* Ws = smem;                         // 512*WPAD halves = 40 KB
    __half* R  = smem + 512 * WPAD;            // union: X tile / D tiles (66 KB)
    float*  Xs = (float*)R;                    // [128][XPAD] floats (17.4 KB)
    __half* Dw = R + (threadIdx.x >> 5) * (16 * DCOLS);  // per-warp D tile

    // Zero the output (poisoned by harness); K2 runs after this kernel.
    {
        int n4 = n_nodes * (F_OUT / 4);
        for (int i = blockIdx.x * blockDim.x + threadIdx.x; i < n4;
             i += gridDim.x * blockDim.x)
            out4[i] = make_float4(0.f, 0.f, 0.f, 0.f);
    }

    // Stage WbigT[j][i] = w[k][i][o],  j = k*32 + o
    for (int idx = threadIdx.x; idx < K16 * F_IN * F_OUT; idx += blockDim.x) {
        int k = idx >> 10, i = (idx >> 5) & 31, o = idx & 31;
        Ws[(k * 32 + o) * WPAD + i] = __float2half_rn(w[idx]);
    }

    const int lane = threadIdx.x & 31;
    const int warp = threadIdx.x >> 5;

    const unsigned bbase = (unsigned)__cvta_generic_to_shared(Ws);
    const int brow  = lane & 7;
    const int bhalf = (lane >> 3) & 1;

    const int mtiles = n_nodes >> 4;          // 3125 (N divisible by 16)
    const int ac = (lane & 3) * 2;

    for (int g = blockIdx.x; g < ngroups; g += gridDim.x) {
        const int n0b = g * 128;
        __syncthreads();   // W staged (1st iter) / previous D flush done

        // Stage X tile: 128 rows x 32 floats, coalesced
        for (int idx = threadIdx.x; idx < 128 * 32; idx += 256) {
            int r = idx >> 5, c = idx & 31;
            int gn = n0b + r;
            Xs[r * XPAD + c] = (gn < n_nodes) ? x[gn * F_IN + c] : 0.f;
        }
        __syncthreads();

        const int mt = g * 8 + warp;
        const bool valid = (mt < mtiles);

        // A fragments from smem: pair p -> row rloc + 8*(p&1),
        // col kc*16 + (lane%4)*2 + 8*(p>>1)
        uint32_t afr[2][4];
        {
            const int rloc = warp * 16 + (lane >> 2);
            #pragma unroll
            for (int kc = 0; kc < 2; kc++)
                #pragma unroll
                for (int p = 0; p < 4; p++) {
                    int r = rloc + ((p & 1) << 3);
                    int cc = kc * 16 + ac + ((p >> 1) << 3);
                    float2 v = *(const float2*)&Xs[r * XPAD + cc];
                    __half2 h = __floats2half2_rn(v.x, v.y);
                    afr[kc][p] = *(uint32_t*)&h;
                }
        }
        __syncthreads();   // X consumed; R now free for D staging

        if (!valid) continue;

        const int n0 = mt << 4;
        __half* d_lo = &Dw[(lane >> 2) * DCOLS + ac];
        __half* d_hi = &Dw[((lane >> 2) + 8) * DCOLS + ac];

        #pragma unroll
        for (int ph = 0; ph < 2; ph++) {      // kx pair {0,1} then {2,3}
            #pragma unroll 4
            for (int ntl = 0; ntl < 32; ntl++) {
                const int nt = ph * 32 + ntl;
                unsigned s0 = bbase + (((nt * 8 + brow) * WPAD) + bhalf * 8) * 2u;
                uint32_t b00, b01, b10, b11;
                asm volatile("ldmatrix.sync.aligned.m8n8.x2.shared.b16 {%0,%1}, [%2];"
                             : "=r"(b00), "=r"(b01) : "r"(s0));
                asm volatile("ldmatrix.sync.aligned.m8n8.x2.shared.b16 {%0,%1}, [%2];"
                             : "=r"(b10), "=r"(b11) : "r"(s0 + 32u));

                float d0 = 0.f, d1 = 0.f, d2 = 0.f, d3 = 0.f;
                asm volatile(
                    "mma.sync.aligned.m16n8k16.row.col.f32.f16.f16.f32 "
                    "{%0,%1,%2,%3}, {%4,%5,%6,%7}, {%8,%9}, {%0,%1,%2,%3};"
                    : "+f"(d0), "+f"(d1), "+f"(d2), "+f"(d3)
                    : "r"(afr[0][0]), "r"(afr[0][1]), "r"(afr[0][2]), "r"(afr[0][3]),
                      "r"(b00), "r"(b01));
                asm volatile(
                    "mma.sync.aligned.m16n8k16.row.col.f32.f16.f16.f32 "
                    "{%0,%1,%2,%3}, {%4,%5,%6,%7}, {%8,%9}, {%0,%1,%2,%3};"
                    : "+f"(d0), "+f"(d1), "+f"(d2), "+f"(d3)
                    : "r"(afr[1][0]), "r"(afr[1][1]), "r"(afr[1][2]), "r"(afr[1][3]),
                      "r"(b10), "r"(b11));

                *(__half2*)&d_lo[ntl * 8] = __floats2half2_rn(d0, d1);
                *(__half2*)&d_hi[ntl * 8] = __floats2half2_rn(d2, d3);
            }
            __syncwarp();

            // Flush into cell-paired layout: per row, per kxl in {0,1},
            // per cell in {0,1,2}: copy D cols [kxl*128 + cell*32, +64)
            // -> Ypair segment (128 B aligned/contiguous).
            // 96 segments x 8 int4; lanes: 4 segments per iteration.
            #pragma unroll
            for (int it = 0; it < 24; it++) {
                int seg = it * 4 + (lane >> 3);       // 0..95
                int qq  = lane & 7;
                int r    = seg / 6;
                int s    = seg - r * 6;
                int kxl  = s / 3;
                int cell = s - kxl * 3;
                const int4 v = *(const int4*)
                    &Dw[r * DCOLS + kxl * 128 + cell * 32 + qq * 8];
                *(int4*)&g_Yp[(size_t)(n0 + r) * YPROW
                              + (ph * 2 + kxl) * 192 + cell * 64 + qq * 8] = v;
            }
            __syncwarp();
        }
    }
}

// ---------------------------------------------------------------------------
// Kernel 2: bilinear gather from cell-paired fp16 Y + fp32 reduction scatter.
// 8 threads per edge. Each thread: TWO 128 B-aligned LDG.128 (kx=jx and
// kx=jx+1 chunks; exactly 1 line each -> 8 corner wavefronts/warp, was 16),
// ky-partials recombined across the (q, q^4) lane pair via shfl_xor(4),
// then one red.global.add.v4.f32 per thread.
// ---------------------------------------------------------------------------
__global__ __launch_bounds__(256) void edge_msg_kernel(
    const int*    __restrict__ ei,   // [2, E] : row0 = dst, row1 = src
    const float2* __restrict__ ea,   // [E]
    float*        __restrict__ out,  // [N, 32]
    int E)
{
    const int t = blockIdx.x * blockDim.x + threadIdx.x;
    const int e = t >> 3;            // 8 threads per edge
    const int q = t & 7;
    if (e >= E) return;

    const int dst = __ldg(&ei[e]);
    const int src = __ldg(&ei[E + e]);
    const float2 a = __ldg(&ea[e]);

    // u = (x+1)/dx in [0,3]; cell j = floor(u) clamped to [0,2]; t = u - j
    float ux = fminf(fmaxf((a.x + 1.0f) * 1.5f, 0.0f), 3.0f);
    float uy = fminf(fmaxf((a.y + 1.0f) * 1.5f, 0.0f), 3.0f);
    int jx = min((int)ux, 2);
    int jy = min((int)uy, 2);
    float tx = ux - (float)jx;
    float ty = uy - (float)jy;
    float sx = 1.0f - tx, sy = 1.0f - ty;

    // chunk(kx) = [ky=jy: 32ch][ky=jy+1: 32ch], 128 B, 128 B-aligned.
    // q<4 -> ky=jy slice, ch base 8*(q&3);  q>=4 -> ky=jy+1 slice.
    const __half* base = g_Yp + (size_t)src * YPROW + jy * 64 + q * 8;
    Half8 v1 = *(const Half8*)(base + jx * 192);         // kx = jx
    Half8 v2 = *(const Half8*)(base + (jx + 1) * 192);   // kx = jx+1

    const float cy = (q & 4) ? ty : sy;
    float p[8];
    #pragma unroll
    for (int j = 0; j < 4; j++) {
        float2 f1 = __half22float2(v1.h[j]);
        float2 f2 = __half22float2(v2.h[j]);
        p[2*j]   = cy * fmaf(tx, f2.x, sx * f1.x);
        p[2*j+1] = cy * fmaf(tx, f2.y, sx * f1.y);
    }

    // Pair (q, q^4) holds the two ky partials for the SAME 8 channels.
    // q&4==0 keeps ch[0:4) of its group; q&4 keeps ch[4:8).
    float r[4];
    #pragma unroll
    for (int j = 0; j < 4; j++) {
        float send = (q & 4) ? p[j] : p[j + 4];
        float recv = __shfl_xor_sync(0xffffffffu, send, 4);
        r[j] = ((q & 4) ? p[j + 4] : p[j]) + recv;
    }

    const int cfin = 8 * (q & 3) + ((q & 4) ? 4 : 0);
    float* dp = out + dst * F_OUT + cfin;   // 16B-aligned
    asm volatile("red.global.add.v4.f32 [%0], {%1, %2, %3, %4};"
                 :: "l"(dp), "f"(r[0]), "f"(r[1]), "f"(r[2]), "f"(r[3])
                 : "memory");
}

// ---------------------------------------------------------------------------
// Launch
// Inputs (metadata order): x_i, x_j, edge_index, edge_attr, weight
// ---------------------------------------------------------------------------
extern "C" void kernel_launch(void* const* d_in, const int* in_sizes, int n_in,
                              void* d_out, int out_size)
{
    const float*  x_j = (const float*) d_in[1];
    const int*    ei  = (const int*)   d_in[2];
    const float2* ea  = (const float2*)d_in[3];
    const float*  w   = (const float*) d_in[4];
    float* out = (float*)d_out;

    const int n_nodes = in_sizes[0] / F_IN;
    const int E       = in_sizes[2] / 2;

    // K1: zero out + build cell-paired Y via tensor cores
    {
        static const int smem_bytes =
            (512 * WPAD + 8 * 16 * DCOLS) * (int)sizeof(__half);  // ~106 KB
        cudaFuncSetAttribute(build_Y_mma,
                             cudaFuncAttributeMaxDynamicSharedMemorySize, smem_bytes);
        int mtiles  = n_nodes >> 4;
        int ngroups = (mtiles + 7) / 8;
        int blocks  = ngroups < 296 ? ngroups : 296;   // 2 blocks/SM
        build_Y_mma<<<blocks, 256, smem_bytes>>>(x_j, w, (float4*)d_out,
                                                 n_nodes, ngroups);
    }

    // K2: edge gather + reduction scatter (8 threads per edge)
    {
        long long threads = (long long)E * 8;
        int blocks = (int)((threads + 255) / 256);
        edge_msg_kernel<<<blocks, 256>>>(ei, ea, out, E);
    }

    (void)n_in; (void)out_size;
}

// round 10
// speedup vs baseline: 1.1471x; 1.1471x over previous
#include <cuda_runtime.h>
#include <cuda_fp16.h>
#include <cstdint>

// Problem constants (shapes fixed by the dataset)
#define MAX_NODES 50000
#define F_IN   32
#define F_OUT  32
#define NB     4
#define K16    (NB * NB)          // 16 basis products
#define YROW   (K16 * F_OUT)      // 512 values per node (j = kx*128 + ky*32 + ch)

// Scratch: Y[n, j] = sum_i x_j[n,i] * W[j>>5, i, j&31]  in fp16 (51.2 MB)
__device__ __half g_Y[(size_t)MAX_NODES * YROW];

struct alignas(16) Half8 { __half2 h[4]; };

// ---------------------------------------------------------------------------
// Kernel 1: zero out, then Y = X @ Wbig via HMMA m16n8k16 (fp16 in, fp32 acc).
//   Wbig[i, j] = w[j>>5][i][j&31]  ->  one GEMM [N,32] x [32,512].
// 256 threads = 8 warps; each warp owns a 16-node m-tile, sweeps 64 n-tiles
// in 2 phases of 32. D fragments are staged in a per-warp smem tile and
// flushed with coalesced 512B row stores.            (round-8, measured best)
// ---------------------------------------------------------------------------
#define WPAD  40    // halves per Ws row (80 B stride: ldmatrix conflict-free)
#define DCOLS 264   // 256 data halves + 8 pad (row stride 528 B, conflict-free)

__global__ __launch_bounds__(256, 2) void build_Y_mma(
    const float* __restrict__ x,     // [N, 32] fp32
    const float* __restrict__ w,     // [16, 32, 32] fp32
    float4*      __restrict__ out4,  // [N*32/4] -- zeroed here
    int n_nodes)
{
    extern __shared__ __half smem[];
    __half* Ws = smem;                                 // 512*WPAD = 40 KB
    __half* Dw = smem + 512 * WPAD +
                 (threadIdx.x >> 5) * (16 * DCOLS);    // per-warp 16x264 tile

    // Zero the output (poisoned by harness); K2 runs after this kernel.
    {
        int n4 = n_nodes * (F_OUT / 4);
        for (int i = blockIdx.x * blockDim.x + threadIdx.x; i < n4;
             i += gridDim.x * blockDim.x)
            out4[i] = make_float4(0.f, 0.f, 0.f, 0.f);
    }

    // Stage WbigT[j][i] = w[k][i][o],  j = k*32 + o  (coalesced global reads)
    for (int idx = threadIdx.x; idx < K16 * F_IN * F_OUT; idx += blockDim.x) {
        int k = idx >> 10, i = (idx >> 5) & 31, o = idx & 31;
        Ws[(k * 32 + o) * WPAD + i] = __float2half_rn(w[idx]);
    }
    __syncthreads();

    const int lane = threadIdx.x & 31;

    // ldmatrix.x2 source addresses for B (lanes 0-7: mat0, 8-15: mat1)
    const unsigned bbase = (unsigned)__cvta_generic_to_shared(Ws);
    const int brow  = lane & 7;          // row within n-tile
    const int bhalf = (lane >> 3) & 1;   // mat1 -> k columns +8

    const int mtiles = n_nodes >> 4;     // N divisible by 16 (50000)
    const int warp_gl = blockIdx.x * 8 + (threadIdx.x >> 5);

    for (int mt = warp_gl; mt < mtiles; mt += gridDim.x * 8) {
        const int n0 = mt << 4;

        // A fragments: 2 k-chunks x 4 pairs, straight from global fp32.
        // pair p: row = n0 + l/4 + 8*(p&1), col = kc*16 + (l%4)*2 + 8*(p>>1)
        uint32_t afr[2][4];
        const int ar = n0 + (lane >> 2);
        const int ac = (lane & 3) * 2;
        #pragma unroll
        for (int kc = 0; kc < 2; kc++)
            #pragma unroll
            for (int p = 0; p < 4; p++) {
                int r = ar + ((p & 1) << 3);
                int cc = kc * 16 + ac + ((p >> 1) << 3);
                float2 v = *(const float2*)&x[r * F_IN + cc];
                __half2 h = __floats2half2_rn(v.x, v.y);
                afr[kc][p] = *(uint32_t*)&h;
            }

        __half* d_lo = &Dw[(lane >> 2) * DCOLS + ac];       // row l/4
        __half* d_hi = &Dw[((lane >> 2) + 8) * DCOLS + ac]; // row l/4 + 8

        #pragma unroll
        for (int ph = 0; ph < 2; ph++) {
            #pragma unroll 4
            for (int ntl = 0; ntl < 32; ntl++) {
                const int nt = ph * 32 + ntl;
                unsigned s0 = bbase +
                    (((nt * 8 + brow) * WPAD) + bhalf * 8) * 2u;
                uint32_t b00, b01, b10, b11;
                asm volatile("ldmatrix.sync.aligned.m8n8.x2.shared.b16 {%0,%1}, [%2];"
                             : "=r"(b00), "=r"(b01) : "r"(s0));
                asm volatile("ldmatrix.sync.aligned.m8n8.x2.shared.b16 {%0,%1}, [%2];"
                             : "=r"(b10), "=r"(b11) : "r"(s0 + 32u));

                float d0 = 0.f, d1 = 0.f, d2 = 0.f, d3 = 0.f;
                asm volatile(
                    "mma.sync.aligned.m16n8k16.row.col.f32.f16.f16.f32 "
                    "{%0,%1,%2,%3}, {%4,%5,%6,%7}, {%8,%9}, {%0,%1,%2,%3};"
                    : "+f"(d0), "+f"(d1), "+f"(d2), "+f"(d3)
                    : "r"(afr[0][0]), "r"(afr[0][1]), "r"(afr[0][2]), "r"(afr[0][3]),
                      "r"(b00), "r"(b01));
                asm volatile(
                    "mma.sync.aligned.m16n8k16.row.col.f32.f16.f16.f32 "
                    "{%0,%1,%2,%3}, {%4,%5,%6,%7}, {%8,%9}, {%0,%1,%2,%3};"
                    : "+f"(d0), "+f"(d1), "+f"(d2), "+f"(d3)
                    : "r"(afr[1][0]), "r"(afr[1][1]), "r"(afr[1][2]), "r"(afr[1][3]),
                      "r"(b10), "r"(b11));

                // Stage D in smem (conflict-free STS.32)
                *(__half2*)&d_lo[ntl * 8] = __floats2half2_rn(d0, d1);
                *(__half2*)&d_hi[ntl * 8] = __floats2half2_rn(d2, d3);
            }
            __syncwarp();

            // Coalesced flush: 16 rows x 512 B; one row per STG.128 instr
            #pragma unroll
            for (int it = 0; it < 16; it++) {
                int i = it * 32 + lane;
                int r = i >> 5, c = i & 31;
                *(int4*)&g_Y[(size_t)(n0 + r) * YROW + ph * 256 + c * 8] =
                    *(const int4*)&Dw[r * DCOLS + c * 8];
            }
            __syncwarp();
        }
    }
}

// ---------------------------------------------------------------------------
// Kernel 2: bilinear gather + fp32 reduction scatter, ORIGINAL Y layout.
// 8 threads per edge. The two ky-corners (jy, jy+1) of each kx are adjacent
// 64 B chunks -> ONE 16 B-aligned LDG.128 per kx per thread covers both
// (1 line when jy is even, 2 when jy==1; expected 10.7 corner wf/warp vs 16).
// ky partials recombined across the (q, q^4) lane pair via shfl_xor(4),
// then one red.global.add.v4.f32 per thread.
// ---------------------------------------------------------------------------
__global__ __launch_bounds__(256) void edge_msg_kernel(
    const int*    __restrict__ ei,   // [2, E] : row0 = dst, row1 = src
    const float2* __restrict__ ea,   // [E]
    float*        __restrict__ out,  // [N, 32]
    int E)
{
    const int t = blockIdx.x * blockDim.x + threadIdx.x;
    const int e = t >> 3;            // 8 threads per edge
    const int q = t & 7;
    if (e >= E) return;

    const int dst = __ldg(&ei[e]);
    const int src = __ldg(&ei[E + e]);
    const float2 a = __ldg(&ea[e]);

    // u = (x+1)/dx in [0,3]; cell j = floor(u) clamped to [0,2]; t = u - j
    float ux = fminf(fmaxf((a.x + 1.0f) * 1.5f, 0.0f), 3.0f);
    float uy = fminf(fmaxf((a.y + 1.0f) * 1.5f, 0.0f), 3.0f);
    int jx = min((int)ux, 2);
    int jy = min((int)uy, 2);
    float tx = ux - (float)jx;
    float ty = uy - (float)jy;
    float sx = 1.0f - tx, sy = 1.0f - ty;

    // 128 B window [ky=jy: 32ch][ky=jy+1: 32ch] at halves jx*128 + jy*32.
    // Thread q takes halves [8q, 8q+8): q<4 -> ky=jy, ch 8q..; q>=4 -> ky=jy+1.
    const __half* base = g_Y + (size_t)src * YROW + jx * 128 + jy * 32 + q * 8;
    Half8 v1 = *(const Half8*)(base);         // kx = jx
    Half8 v2 = *(const Half8*)(base + 128);   // kx = jx+1

    const float cy = (q & 4) ? ty : sy;
    float p[8];
    #pragma unroll
    for (int j = 0; j < 4; j++) {
        float2 f1 = __half22float2(v1.h[j]);
        float2 f2 = __half22float2(v2.h[j]);
        p[2*j]   = cy * fmaf(tx, f2.x, sx * f1.x);
        p[2*j+1] = cy * fmaf(tx, f2.y, sx * f1.y);
    }

    // Pair (q, q^4) holds the two ky partials for the SAME 8 channels.
    // q&4==0 keeps ch[0:4) of its group; q&4 keeps ch[4:8).
    float r[4];
    #pragma unroll
    for (int j = 0; j < 4; j++) {
        float send = (q & 4) ? p[j] : p[j + 4];
        float recv = __shfl_xor_sync(0xffffffffu, send, 4);
        r[j] = ((q & 4) ? p[j + 4] : p[j]) + recv;
    }

    const int cfin = 8 * (q & 3) + ((q & 4) ? 4 : 0);
    float* dp = out + dst * F_OUT + cfin;   // 16B-aligned
    asm volatile("red.global.add.v4.f32 [%0], {%1, %2, %3, %4};"
                 :: "l"(dp), "f"(r[0]), "f"(r[1]), "f"(r[2]), "f"(r[3])
                 : "memory");
}

// ---------------------------------------------------------------------------
// Launch
// Inputs (metadata order): x_i, x_j, edge_index, edge_attr, weight
// ---------------------------------------------------------------------------
extern "C" void kernel_launch(void* const* d_in, const int* in_sizes, int n_in,
                              void* d_out, int out_size)
{
    const float*  x_j = (const float*) d_in[1];
    const int*    ei  = (const int*)   d_in[2];
    const float2* ea  = (const float2*)d_in[3];
    const float*  w   = (const float*) d_in[4];
    float* out = (float*)d_out;

    const int n_nodes = in_sizes[0] / F_IN;
    const int E       = in_sizes[2] / 2;

    // K1: zero out + build Y via tensor cores, smem-staged coalesced stores
    {
        static const int smem_bytes =
            (512 * WPAD + 8 * 16 * DCOLS) * (int)sizeof(__half);  // ~106 KB
        cudaFuncSetAttribute(build_Y_mma,
                             cudaFuncAttributeMaxDynamicSharedMemorySize, smem_bytes);
        int mtiles = n_nodes >> 4;                 // 3125
        int blocks = (mtiles + 7) / 8;
        if (blocks > 296) blocks = 296;            // 2 blocks/SM, grid-stride
        build_Y_mma<<<blocks, 256, smem_bytes>>>(x_j, w, (float4*)d_out, n_nodes);
    }

    // K2: edge gather + reduction scatter (8 threads per edge)
    {
        long long threads = (long long)E * 8;
        int blocks = (int)((threads + 255) / 256);
        edge_msg_kernel<<<blocks, 256>>>(ei, ea, out, E);
    }

    (void)n_in; (void)out_size;
}

// round 11
// speedup vs baseline: 1.3448x; 1.1724x over previous
#include <cuda_runtime.h>
#include <cuda_fp16.h>
#include <cstdint>

// Problem constants (shapes fixed by the dataset)
#define MAX_NODES 50000
#define F_IN   32
#define F_OUT  32
#define NB     4
#define K16    (NB * NB)          // 16 basis products
#define YROW   (K16 * F_OUT)      // 512 values per node (j = kx*128 + ky*32 + ch)

// Scratch: Y[n, j] = sum_i x_j[n,i] * W[j>>5, i, j&31]  in fp16 (51.2 MB)
__device__ __half g_Y[(size_t)MAX_NODES * YROW];

struct alignas(8) Half4 { __half2 a, b; };

// ---------------------------------------------------------------------------
// Kernel 1: zero out, then Y = X @ Wbig via HMMA m16n8k16 (fp16 in, fp32 acc).
//   Wbig[i, j] = w[j>>5][i][j&31]  ->  one GEMM [N,32] x [32,512].
// 256 threads = 8 warps; each warp owns a 16-node m-tile, sweeps 64 n-tiles
// in 2 phases of 32. D fragments are staged in a per-warp smem tile and
// flushed with coalesced 512B row stores.            (round-8, measured best)
// ---------------------------------------------------------------------------
#define WPAD  40    // halves per Ws row (80 B stride: ldmatrix conflict-free)
#define DCOLS 264   // 256 data halves + 8 pad (row stride 528 B, conflict-free)

__global__ __launch_bounds__(256, 2) void build_Y_mma(
    const float* __restrict__ x,     // [N, 32] fp32
    const float* __restrict__ w,     // [16, 32, 32] fp32
    float4*      __restrict__ out4,  // [N*32/4] -- zeroed here
    int n_nodes)
{
    extern __shared__ __half smem[];
    __half* Ws = smem;                                 // 512*WPAD = 40 KB
    __half* Dw = smem + 512 * WPAD +
                 (threadIdx.x >> 5) * (16 * DCOLS);    // per-warp 16x264 tile

    // Zero the output (poisoned by harness); K2 runs after this kernel.
    {
        int n4 = n_nodes * (F_OUT / 4);
        for (int i = blockIdx.x * blockDim.x + threadIdx.x; i < n4;
             i += gridDim.x * blockDim.x)
            out4[i] = make_float4(0.f, 0.f, 0.f, 0.f);
    }

    // Stage WbigT[j][i] = w[k][i][o],  j = k*32 + o  (coalesced global reads)
    for (int idx = threadIdx.x; idx < K16 * F_IN * F_OUT; idx += blockDim.x) {
        int k = idx >> 10, i = (idx >> 5) & 31, o = idx & 31;
        Ws[(k * 32 + o) * WPAD + i] = __float2half_rn(w[idx]);
    }
    __syncthreads();

    const int lane = threadIdx.x & 31;

    // ldmatrix.x2 source addresses for B (lanes 0-7: mat0, 8-15: mat1)
    const unsigned bbase = (unsigned)__cvta_generic_to_shared(Ws);
    const int brow  = lane & 7;          // row within n-tile
    const int bhalf = (lane >> 3) & 1;   // mat1 -> k columns +8

    const int mtiles = n_nodes >> 4;     // N divisible by 16 (50000)
    const int warp_gl = blockIdx.x * 8 + (threadIdx.x >> 5);

    for (int mt = warp_gl; mt < mtiles; mt += gridDim.x * 8) {
        const int n0 = mt << 4;

        // A fragments: 2 k-chunks x 4 pairs, straight from global fp32.
        // pair p: row = n0 + l/4 + 8*(p&1), col = kc*16 + (l%4)*2 + 8*(p>>1)
        uint32_t afr[2][4];
        const int ar = n0 + (lane >> 2);
        const int ac = (lane & 3) * 2;
        #pragma unroll
        for (int kc = 0; kc < 2; kc++)
            #pragma unroll
            for (int p = 0; p < 4; p++) {
                int r = ar + ((p & 1) << 3);
                int cc = kc * 16 + ac + ((p >> 1) << 3);
                float2 v = *(const float2*)&x[r * F_IN + cc];
                __half2 h = __floats2half2_rn(v.x, v.y);
                afr[kc][p] = *(uint32_t*)&h;
            }

        __half* d_lo = &Dw[(lane >> 2) * DCOLS + ac];       // row l/4
        __half* d_hi = &Dw[((lane >> 2) + 8) * DCOLS + ac]; // row l/4 + 8

        #pragma unroll
        for (int ph = 0; ph < 2; ph++) {
            #pragma unroll 4
            for (int ntl = 0; ntl < 32; ntl++) {
                const int nt = ph * 32 + ntl;
                unsigned s0 = bbase +
                    (((nt * 8 + brow) * WPAD) + bhalf * 8) * 2u;
                uint32_t b00, b01, b10, b11;
                asm volatile("ldmatrix.sync.aligned.m8n8.x2.shared.b16 {%0,%1}, [%2];"
                             : "=r"(b00), "=r"(b01) : "r"(s0));
                asm volatile("ldmatrix.sync.aligned.m8n8.x2.shared.b16 {%0,%1}, [%2];"
                             : "=r"(b10), "=r"(b11) : "r"(s0 + 32u));

                float d0 = 0.f, d1 = 0.f, d2 = 0.f, d3 = 0.f;
                asm volatile(
                    "mma.sync.aligned.m16n8k16.row.col.f32.f16.f16.f32 "
                    "{%0,%1,%2,%3}, {%4,%5,%6,%7}, {%8,%9}, {%0,%1,%2,%3};"
                    : "+f"(d0), "+f"(d1), "+f"(d2), "+f"(d3)
                    : "r"(afr[0][0]), "r"(afr[0][1]), "r"(afr[0][2]), "r"(afr[0][3]),
                      "r"(b00), "r"(b01));
                asm volatile(
                    "mma.sync.aligned.m16n8k16.row.col.f32.f16.f16.f32 "
                    "{%0,%1,%2,%3}, {%4,%5,%6,%7}, {%8,%9}, {%0,%1,%2,%3};"
                    : "+f"(d0), "+f"(d1), "+f"(d2), "+f"(d3)
                    : "r"(afr[1][0]), "r"(afr[1][1]), "r"(afr[1][2]), "r"(afr[1][3]),
                      "r"(b10), "r"(b11));

                // Stage D in smem (conflict-free STS.32)
                *(__half2*)&d_lo[ntl * 8] = __floats2half2_rn(d0, d1);
                *(__half2*)&d_hi[ntl * 8] = __floats2half2_rn(d2, d3);
            }
            __syncwarp();

            // Coalesced flush: 16 rows x 512 B; one row per STG.128 instr
            #pragma unroll
            for (int it = 0; it < 16; it++) {
                int i = it * 32 + lane;
                int r = i >> 5, c = i & 31;
                *(int4*)&g_Y[(size_t)(n0 + r) * YROW + ph * 256 + c * 8] =
                    *(const int4*)&Dw[r * DCOLS + c * 8];
            }
            __syncwarp();
        }
    }
}

// ---------------------------------------------------------------------------
// Kernel 2: bilinear gather from fp16 Y + vectorized fp32 reduction scatter.
// Round-8 access shape (measured best: 8 threads/edge, 4x LDG.64 corners,
// one RED.v4 per thread) but TWO edges per thread (e and e + E/2) to double
// memory-level parallelism: 8 independent corner loads in flight per thread
// before any math. Index/attr reads stay fully coalesced in both halves.
// ---------------------------------------------------------------------------
__global__ __launch_bounds__(256) void edge_msg_kernel(
    const int*    __restrict__ ei,   // [2, E] : row0 = dst, row1 = src
    const float2* __restrict__ ea,   // [E]
    float*        __restrict__ out,  // [N, 32]
    int E, int Ehalf)
{
    const int t = blockIdx.x * blockDim.x + threadIdx.x;
    const int e0 = t >> 3;           // 8 threads per edge
    const int c = (t & 7) << 2;      // base of this thread's 4 outputs
    if (e0 >= Ehalf) return;
    const int e1 = e0 + Ehalf;
    const bool has1 = (e1 < E);

    // ---- gather both edges' metadata (independent loads) ----
    const int dst0 = __ldg(&ei[e0]);
    const int src0 = __ldg(&ei[E + e0]);
    const float2 a0 = __ldg(&ea[e0]);
    const int dst1 = has1 ? __ldg(&ei[e1]) : 0;
    const int src1 = has1 ? __ldg(&ei[E + e1]) : 0;
    const float2 a1 = has1 ? __ldg(&ea[e1]) : make_float2(0.f, 0.f);

    // ---- coefficients edge 0 ----
    float ux0 = fminf(fmaxf((a0.x + 1.0f) * 1.5f, 0.0f), 3.0f);
    float uy0 = fminf(fmaxf((a0.y + 1.0f) * 1.5f, 0.0f), 3.0f);
    int jx0 = min((int)ux0, 2), jy0 = min((int)uy0, 2);
    float tx0 = ux0 - (float)jx0, ty0 = uy0 - (float)jy0;
    float sx0 = 1.0f - tx0, sy0 = 1.0f - ty0;
    const float c00_0 = sx0 * sy0, c01_0 = sx0 * ty0,
                c10_0 = tx0 * sy0, c11_0 = tx0 * ty0;

    // ---- coefficients edge 1 ----
    float ux1 = fminf(fmaxf((a1.x + 1.0f) * 1.5f, 0.0f), 3.0f);
    float uy1 = fminf(fmaxf((a1.y + 1.0f) * 1.5f, 0.0f), 3.0f);
    int jx1 = min((int)ux1, 2), jy1 = min((int)uy1, 2);
    float tx1 = ux1 - (float)jx1, ty1 = uy1 - (float)jy1;
    float sx1 = 1.0f - tx1, sy1 = 1.0f - ty1;
    const float c00_1 = sx1 * sy1, c01_1 = sx1 * ty1,
                c10_1 = tx1 * sy1, c11_1 = tx1 * ty1;

    // ---- issue all 8 corner loads back-to-back (max MLP) ----
    // k = kx*4 + ky ; corner (jx,jy): +32 elems per ky step, +128 per kx step
    const __half* Y0 = &g_Y[(size_t)src0 * YROW + (jx0 * NB + jy0) * F_OUT + c];
    const __half* Y1 = &g_Y[(size_t)(has1 ? src1 : src0) * YROW
                            + (jx1 * NB + jy1) * F_OUT + c];
    Half4 v00_0 = *(const Half4*)(Y0);
    Half4 v01_0 = *(const Half4*)(Y0 + 32);
    Half4 v10_0 = *(const Half4*)(Y0 + 128);
    Half4 v11_0 = *(const Half4*)(Y0 + 160);
    Half4 v00_1 = *(const Half4*)(Y1);
    Half4 v01_1 = *(const Half4*)(Y1 + 32);
    Half4 v10_1 = *(const Half4*)(Y1 + 128);
    Half4 v11_1 = *(const Half4*)(Y1 + 160);

    // ---- edge 0 math + scatter ----
    {
        float2 f00a = __half22float2(v00_0.a), f00b = __half22float2(v00_0.b);
        float2 f01a = __half22float2(v01_0.a), f01b = __half22float2(v01_0.b);
        float2 f10a = __half22float2(v10_0.a), f10b = __half22float2(v10_0.b);
        float2 f11a = __half22float2(v11_0.a), f11b = __half22float2(v11_0.b);
        float r0 = c00_0*f00a.x + c01_0*f01a.x + c10_0*f10a.x + c11_0*f11a.x;
        float r1 = c00_0*f00a.y + c01_0*f01a.y + c10_0*f10a.y + c11_0*f11a.y;
        float r2 = c00_0*f00b.x + c01_0*f01b.x + c10_0*f10b.x + c11_0*f11b.x;
        float r3 = c00_0*f00b.y + c01_0*f01b.y + c10_0*f10b.y + c11_0*f11b.y;
        float* dp = out + dst0 * F_OUT + c;   // 16B-aligned
        asm volatile("red.global.add.v4.f32 [%0], {%1, %2, %3, %4};"
                     :: "l"(dp), "f"(r0), "f"(r1), "f"(r2), "f"(r3)
                     : "memory");
    }

    // ---- edge 1 math + scatter ----
    if (has1) {
        float2 f00a = __half22float2(v00_1.a), f00b = __half22float2(v00_1.b);
        float2 f01a = __half22float2(v01_1.a), f01b = __half22float2(v01_1.b);
        float2 f10a = __half22float2(v10_1.a), f10b = __half22float2(v10_1.b);
        float2 f11a = __half22float2(v11_1.a), f11b = __half22float2(v11_1.b);
        float r0 = c00_1*f00a.x + c01_1*f01a.x + c10_1*f10a.x + c11_1*f11a.x;
        float r1 = c00_1*f00a.y + c01_1*f01a.y + c10_1*f10a.y + c11_1*f11a.y;
        float r2 = c00_1*f00b.x + c01_1*f01b.x + c10_1*f10b.x + c11_1*f11b.x;
        float r3 = c00_1*f00b.y + c01_1*f01b.y + c10_1*f10b.y + c11_1*f11b.y;
        float* dp = out + dst1 * F_OUT + c;   // 16B-aligned
        asm volatile("red.global.add.v4.f32 [%0], {%1, %2, %3, %4};"
                     :: "l"(dp), "f"(r0), "f"(r1), "f"(r2), "f"(r3)
                     : "memory");
    }
}

// ---------------------------------------------------------------------------
// Launch
// Inputs (metadata order): x_i, x_j, edge_index, edge_attr, weight
// ---------------------------------------------------------------------------
extern "C" void kernel_launch(void* const* d_in, const int* in_sizes, int n_in,
                              void* d_out, int out_size)
{
    const float*  x_j = (const float*) d_in[1];
    const int*    ei  = (const int*)   d_in[2];
    const float2* ea  = (const float2*)d_in[3];
    const float*  w   = (const float*) d_in[4];
    float* out = (float*)d_out;

    const int n_nodes = in_sizes[0] / F_IN;
    const int E       = in_sizes[2] / 2;

    // K1: zero out + build Y via tensor cores, smem-staged coalesced stores
    {
        static const int smem_bytes =
            (512 * WPAD + 8 * 16 * DCOLS) * (int)sizeof(__half);  // ~106 KB
        cudaFuncSetAttribute(build_Y_mma,
                             cudaFuncAttributeMaxDynamicSharedMemorySize, smem_bytes);
        int mtiles = n_nodes >> 4;                 // 3125
        int blocks = (mtiles + 7) / 8;
        if (blocks > 296) blocks = 296;            // 2 blocks/SM, grid-stride
        build_Y_mma<<<blocks, 256, smem_bytes>>>(x_j, w, (float4*)d_out, n_nodes);
    }

    // K2: edge gather + reduction scatter, 2 edges per thread for MLP
    {
        int Ehalf = (E + 1) >> 1;
        long long threads = (long long)Ehalf * 8;
        int blocks = (int)((threads + 255) / 256);
        edge_msg_kernel<<<blocks, 256>>>(ei, ea, out, E, Ehalf);
    }

    (void)n_in; (void)out_size;
}